// round 8
// baseline (speedup 1.0000x reference)
#include <cuda_runtime.h>
#include <cstdint>

// ChessboardLayer: (B,H,W,C)=(32,256,256,32) fp32 space-to-depth into 8x8 cells.
// Pure 4KiB-block transpose:
//   in  chunk id q = br*256 + i*8 + c
//   out chunk id o = br*256 + c*32 + i
//
// R7: R5 layout (fastest kernel so far: each CTA owns 4 consecutive OUTPUT
// chunks -> 16 KiB contiguous write; 4 batched reads at 32 KiB stride),
// but DEFAULT store policy instead of .cs: let L2 writeback aggregate the
// dirty-line drain into better row-batched DRAM bursts instead of eager
// evict-first in issue order. Loads stay .cs (single-use stream).

__global__ void __launch_bounds__(256, 8)
chessboard_kernel(const float4* __restrict__ in, float4* __restrict__ out) {
    unsigned obase = blockIdx.x * 4u;    // first output chunk id
    unsigned t     = threadIdx.x;

    // o = obase + k. Aligned 4-group: br, c shared; i = i0 + k.
    unsigned i0 = obase & 31u;
    unsigned c  = (obase >> 5) & 7u;
    unsigned br = obase >> 8;

    // input chunk q(k) = br*256 + (i0+k)*8 + c  -> stride 8 chunks (2048 f4)
    const float4* ib = in + (size_t)(br * 256u + i0 * 8u + c) * 256u + t;

    float4 v0 = __ldcs(ib + 0u * 2048u);
    float4 v1 = __ldcs(ib + 1u * 2048u);
    float4 v2 = __ldcs(ib + 2u * 2048u);
    float4 v3 = __ldcs(ib + 3u * 2048u);

    float4* ob = out + (size_t)obase * 256u + t;
    ob[0u * 256u] = v0;
    ob[1u * 256u] = v1;
    ob[2u * 256u] = v2;
    ob[3u * 256u] = v3;
}

extern "C" void kernel_launch(void* const* d_in, const int* in_sizes, int n_in,
                              void* d_out, int out_size) {
    const float4* in  = (const float4*)d_in[0];
    float4*       out = (float4*)d_out;
    // 65536 output chunks / 4 per CTA = 16384 CTAs
    chessboard_kernel<<<16384, 256>>>(in, out);
}

// round 9
// speedup vs baseline: 1.0086x; 1.0086x over previous
#include <cuda_runtime.h>
#include <cstdint>

// ChessboardLayer: (B,H,W,C)=(32,256,256,32) fp32 space-to-depth into 8x8 cells.
// Pure 4KiB-block transpose:
//   in  chunk id q = br*256 + i*8 + c
//   out chunk id o = br*256 + c*32 + i
//
// FINAL (R5 layout, re-verified): each CTA owns 4 consecutive OUTPUT chunks:
//   write: 16 KiB fully contiguous (.cs streaming)
//   read : 4 x 4 KiB streams at 32 KiB stride, front-batched (MLP=4)
// Measured 74.98us kernel / ~6.43 TB/s = 80% of HBM spec — the chip's
// mixed read+write stream ceiling (confirmed across 7 layout/policy variants,
// all within 75-79us; LTS cap is path-independent so TMA cannot beat it).

__global__ void __launch_bounds__(256, 8)
chessboard_kernel(const float4* __restrict__ in, float4* __restrict__ out) {
    unsigned obase = blockIdx.x * 4u;    // first output chunk id
    unsigned t     = threadIdx.x;

    // o = obase + k. Aligned 4-group: br, c shared; i = i0 + k.
    unsigned i0 = obase & 31u;
    unsigned c  = (obase >> 5) & 7u;
    unsigned br = obase >> 8;

    // input chunk q(k) = br*256 + (i0+k)*8 + c  -> stride 8 chunks (2048 f4)
    const float4* ib = in + (size_t)(br * 256u + i0 * 8u + c) * 256u + t;

    float4 v0 = __ldcs(ib + 0u * 2048u);
    float4 v1 = __ldcs(ib + 1u * 2048u);
    float4 v2 = __ldcs(ib + 2u * 2048u);
    float4 v3 = __ldcs(ib + 3u * 2048u);

    float4* ob = out + (size_t)obase * 256u + t;
    __stcs(ob + 0u * 256u, v0);
    __stcs(ob + 1u * 256u, v1);
    __stcs(ob + 2u * 256u, v2);
    __stcs(ob + 3u * 256u, v3);
}

extern "C" void kernel_launch(void* const* d_in, const int* in_sizes, int n_in,
                              void* d_out, int out_size) {
    const float4* in  = (const float4*)d_in[0];
    float4*       out = (float4*)d_out;
    // 65536 output chunks / 4 per CTA = 16384 CTAs
    chessboard_kernel<<<16384, 256>>>(in, out);
}